// round 2
// baseline (speedup 1.0000x reference)
#include <cuda_runtime.h>

// ---------------------------------------------------------------------------
// LSTM forward: B=32, T=512, I=512, H=1024, fp32.
// Phase 1: xg[m][j] = sum_k x[m][k] * Wx[j][k] + bx[j] + bh[j]   (m = b*T + t)
// Phase 2: 512 sequential steps:
//   gates[b][j] = xg[b,t,j] + sum_k h[b][k] * Wh[j][k]
//   i,f,g,o = split(gates); c = sig(f)*c + sig(i)*tanh(g); h = sig(o)*tanh(c)
// ---------------------------------------------------------------------------

#define BDIM 32
#define TDIM 512
#define IDIM 512
#define HDIM 1024
#define G4   4096   // 4*H

// Scratch (device globals: allocation-free per harness rules)
__device__ float g_xg[(size_t)BDIM * TDIM * G4];     // [B*T, 4H], 256 MB
__device__ float g_h[2][HDIM * BDIM];                // h transposed: [k][b], double-buffered
__device__ float g_c[HDIM * BDIM];                   // c transposed: [n][b]

// ---------------------------------------------------------------------------
__global__ void init_state_kernel() {
    int i = blockIdx.x * blockDim.x + threadIdx.x;
    if (i < HDIM * BDIM) {
        g_h[0][i] = 0.0f;
        g_c[i]    = 0.0f;
    }
}

// ---------------------------------------------------------------------------
// Phase 1 GEMM: C[16384,4096] = X[16384,512] * Wx[4096,512]^T + (bx+bh)
// 128x128 block tile, BK=16, 256 threads, 8x8 per thread.
// ---------------------------------------------------------------------------
__global__ void __launch_bounds__(256, 2) gemm_xg_kernel(
    const float* __restrict__ X,
    const float* __restrict__ Wx,
    const float* __restrict__ bx,
    const float* __restrict__ bh)
{
    __shared__ float As[16][128];
    __shared__ float Bs[16][128];

    const int tid = threadIdx.x;
    const int bm  = blockIdx.y * 128;
    const int bn  = blockIdx.x * 128;

    const int lr = tid >> 2;          // 0..63 (row within tile, two rows per thread)
    const int lc = (tid & 3) << 2;    // 0,4,8,12 (k offset)
    const int tm = (tid >> 4) << 3;   // output row base (0..120)
    const int tn = (tid & 15) << 3;   // output col base (0..120)

    float acc[8][8];
#pragma unroll
    for (int i = 0; i < 8; i++)
#pragma unroll
        for (int j = 0; j < 8; j++) acc[i][j] = 0.0f;

    for (int k0 = 0; k0 < IDIM; k0 += 16) {
#pragma unroll
        for (int r = 0; r < 2; r++) {
            const int row = lr + r * 64;
            float4 va = *(const float4*)(X  + (size_t)(bm + row) * IDIM + k0 + lc);
            As[lc + 0][row] = va.x;
            As[lc + 1][row] = va.y;
            As[lc + 2][row] = va.z;
            As[lc + 3][row] = va.w;
            float4 vb = *(const float4*)(Wx + (size_t)(bn + row) * IDIM + k0 + lc);
            Bs[lc + 0][row] = vb.x;
            Bs[lc + 1][row] = vb.y;
            Bs[lc + 2][row] = vb.z;
            Bs[lc + 3][row] = vb.w;
        }
        __syncthreads();

#pragma unroll
        for (int kk = 0; kk < 16; kk++) {
            float a[8], b[8];
            float4 a0 = *(const float4*)(&As[kk][tm]);
            float4 a1 = *(const float4*)(&As[kk][tm + 4]);
            float4 b0 = *(const float4*)(&Bs[kk][tn]);
            float4 b1 = *(const float4*)(&Bs[kk][tn + 4]);
            a[0]=a0.x; a[1]=a0.y; a[2]=a0.z; a[3]=a0.w;
            a[4]=a1.x; a[5]=a1.y; a[6]=a1.z; a[7]=a1.w;
            b[0]=b0.x; b[1]=b0.y; b[2]=b0.z; b[3]=b0.w;
            b[4]=b1.x; b[5]=b1.y; b[6]=b1.z; b[7]=b1.w;
#pragma unroll
            for (int i = 0; i < 8; i++)
#pragma unroll
                for (int j = 0; j < 8; j++)
                    acc[i][j] = fmaf(a[i], b[j], acc[i][j]);
        }
        __syncthreads();
    }

    float bias[8];
#pragma unroll
    for (int j = 0; j < 8; j++)
        bias[j] = bx[bn + tn + j] + bh[bn + tn + j];

#pragma unroll
    for (int i = 0; i < 8; i++) {
        float* o = g_xg + (size_t)(bm + tm + i) * G4 + bn + tn;
#pragma unroll
        for (int j = 0; j < 8; j++)
            o[j] = acc[i][j] + bias[j];
    }
}

// ---------------------------------------------------------------------------
// Phase 2 step kernel: 128 blocks x 256 threads.
// warp w of block cb owns cell n = cb*8 + w (all 32 batches = lanes).
// Wh rows for gates i/f/g/o of cell n are read as uniform float4 broadcasts
// (L2-resident after step 0); h is kept transposed [k][b] so lane loads are
// coalesced 128B. h double-buffered across steps (inter-block race avoidance).
// ---------------------------------------------------------------------------
__global__ void __launch_bounds__(256) lstm_step_kernel(
    const float* __restrict__ Wh,
    float* __restrict__ out,
    int t)
{
    const int lane = threadIdx.x & 31;   // batch index b
    const int w    = threadIdx.x >> 5;   // warp id
    const int n    = (blockIdx.x << 3) + w;   // cell index 0..1023

    const float* __restrict__ hin  = g_h[t & 1];
    float* __restrict__       hout = g_h[(t + 1) & 1];

    const float4* __restrict__ wi = (const float4*)(Wh + (size_t)n          * HDIM);
    const float4* __restrict__ wf = (const float4*)(Wh + (size_t)(n + 1024) * HDIM);
    const float4* __restrict__ wg = (const float4*)(Wh + (size_t)(n + 2048) * HDIM);
    const float4* __restrict__ wo = (const float4*)(Wh + (size_t)(n + 3072) * HDIM);

    float ai = 0.0f, af = 0.0f, ag = 0.0f, ao = 0.0f;
    const float* hp = hin + lane;

#pragma unroll 4
    for (int k4 = 0; k4 < HDIM / 4; k4++) {
        float4 vi = __ldg(wi + k4);
        float4 vf = __ldg(wf + k4);
        float4 vg = __ldg(wg + k4);
        float4 vo = __ldg(wo + k4);
        float h0 = __ldg(hp + 0);
        float h1 = __ldg(hp + 32);
        float h2 = __ldg(hp + 64);
        float h3 = __ldg(hp + 96);
        hp += 128;
        ai = fmaf(h0, vi.x, ai); af = fmaf(h0, vf.x, af);
        ag = fmaf(h0, vg.x, ag); ao = fmaf(h0, vo.x, ao);
        ai = fmaf(h1, vi.y, ai); af = fmaf(h1, vf.y, af);
        ag = fmaf(h1, vg.y, ag); ao = fmaf(h1, vo.y, ao);
        ai = fmaf(h2, vi.z, ai); af = fmaf(h2, vf.z, af);
        ag = fmaf(h2, vg.z, ag); ao = fmaf(h2, vo.z, ao);
        ai = fmaf(h3, vi.w, ai); af = fmaf(h3, vf.w, af);
        ag = fmaf(h3, vg.w, ag); ao = fmaf(h3, vo.w, ao);
    }

    // add precomputed input projection (+biases, already folded in)
    const size_t xb = ((size_t)lane * TDIM + t) * G4 + n;
    const float gi = ai + g_xg[xb];
    const float gf = af + g_xg[xb + 1024];
    const float gg = ag + g_xg[xb + 2048];
    const float go = ao + g_xg[xb + 3072];

    // accurate activations (tanh.approx max-rel ~1e-3 is too close to threshold)
    const float si = __fdividef(1.0f, 1.0f + __expf(-gi));
    const float sf = __fdividef(1.0f, 1.0f + __expf(-gf));
    const float so = __fdividef(1.0f, 1.0f + __expf(-go));
    const float tg = tanhf(gg);

    const int ci = (n << 5) + lane;
    const float c = sf * g_c[ci] + si * tg;
    g_c[ci] = c;
    const float h = so * tanhf(c);

    hout[ci] = h;                                          // coalesced [n][b]
    out[((size_t)lane * TDIM + t) * HDIM + n] = h;         // [B,T,H]
}

// ---------------------------------------------------------------------------
extern "C" void kernel_launch(void* const* d_in, const int* in_sizes, int n_in,
                              void* d_out, int out_size)
{
    const float* x  = (const float*)d_in[0];   // [B,T,I]
    const float* Wx = (const float*)d_in[1];   // [4H,I]
    const float* bx = (const float*)d_in[2];   // [4H]
    const float* Wh = (const float*)d_in[3];   // [4H,H]
    const float* bh = (const float*)d_in[4];   // [4H]
    float* out = (float*)d_out;                // [B,T,H]

    (void)in_sizes; (void)n_in; (void)out_size;

    init_state_kernel<<<(HDIM * BDIM + 255) / 256, 256>>>();

    dim3 ggrid(G4 / 128, (BDIM * TDIM) / 128);   // (32, 128)
    gemm_xg_kernel<<<ggrid, 256>>>(x, Wx, bx, bh);

    for (int t = 0; t < TDIM; t++)
        lstm_step_kernel<<<128, 256>>>(Wh, out, t);
}

// round 3
// speedup vs baseline: 2.1905x; 2.1905x over previous
#include <cuda_runtime.h>

// ---------------------------------------------------------------------------
// LSTM forward: B=32, T=512, I=512, H=1024, fp32.
// Phase 1: xg = x @ Wx^T + bx + bh   (tiled fp32 GEMM, unchanged)
// Phase 2: ONE persistent kernel, 128 blocks (1/SM, all resident):
//   - block owns 8 cells; their 32 Wh rows live in smem for all 512 steps,
//     pre-interleaved as (i,f) and (g,o) f32x2 pairs
//   - h double-buffered in global as {h,h} float2 (feeds fma.rn.f32x2 directly)
//   - c state in registers for the whole sequence
//   - software grid barrier (atomic counter + acquire spin) between steps
// Phase 3: 32x32 tiled transpose [t*H+n][b] -> [b][t*H+n]
// ---------------------------------------------------------------------------

#define BDIM 32
#define TDIM 512
#define IDIM 512
#define HDIM 1024
#define G4   4096                 // 4*H
#define NBLK 128                  // persistent blocks (<= 148 SMs, 1/SM)
#define CELLS_PER_BLK 8

typedef unsigned long long ull;
struct __align__(16) ull2 { ull x, y; };

// Scratch (device globals: allocation-free per harness rules)
__device__ float g_xg[(size_t)BDIM * TDIM * G4];          // [B,T,4H]  256 MB
__device__ ull   g_hdup[2][HDIM * BDIM];                  // {h,h} packed, [n][b]
__device__ float g_hist[(size_t)TDIM * HDIM * BDIM];      // [t][n][b]  64 MB
__device__ int   g_count;                                 // barrier counter

__device__ __forceinline__ ull ffma2(ull a, ull b, ull c) {
    ull d;
    asm("fma.rn.f32x2 %0, %1, %2, %3;" : "=l"(d) : "l"(a), "l"(b), "l"(c));
    return d;
}
__device__ __forceinline__ ull pack2(float x, float y) {
    ull d;
    asm("mov.b64 %0, {%1, %2};" : "=l"(d) : "f"(x), "f"(y));
    return d;
}
__device__ __forceinline__ float2 unpack2(ull v) {
    float2 r;
    asm("mov.b64 {%0, %1}, %2;" : "=f"(r.x), "=f"(r.y) : "l"(v));
    return r;
}
__device__ __forceinline__ int ld_acquire(const int* p) {
    int v;
    asm volatile("ld.global.acquire.gpu.b32 %0, [%1];" : "=r"(v) : "l"(p));
    return v;
}

// ---------------------------------------------------------------------------
__global__ void init_state_kernel() {
    int i = blockIdx.x * blockDim.x + threadIdx.x;
    if (i < HDIM * BDIM) g_hdup[0][i] = 0ULL;
    if (i == 0) g_count = 0;
}

// ---------------------------------------------------------------------------
// Phase 1 GEMM: C[16384,4096] = X[16384,512] * Wx[4096,512]^T + (bx+bh)
// ---------------------------------------------------------------------------
__global__ void __launch_bounds__(256, 2) gemm_xg_kernel(
    const float* __restrict__ X,
    const float* __restrict__ Wx,
    const float* __restrict__ bx,
    const float* __restrict__ bh)
{
    __shared__ float As[16][128];
    __shared__ float Bs[16][128];

    const int tid = threadIdx.x;
    const int bm  = blockIdx.y * 128;
    const int bn  = blockIdx.x * 128;

    const int lr = tid >> 2;
    const int lc = (tid & 3) << 2;
    const int tm = (tid >> 4) << 3;
    const int tn = (tid & 15) << 3;

    float acc[8][8];
#pragma unroll
    for (int i = 0; i < 8; i++)
#pragma unroll
        for (int j = 0; j < 8; j++) acc[i][j] = 0.0f;

    for (int k0 = 0; k0 < IDIM; k0 += 16) {
#pragma unroll
        for (int r = 0; r < 2; r++) {
            const int row = lr + r * 64;
            float4 va = *(const float4*)(X  + (size_t)(bm + row) * IDIM + k0 + lc);
            As[lc + 0][row] = va.x;
            As[lc + 1][row] = va.y;
            As[lc + 2][row] = va.z;
            As[lc + 3][row] = va.w;
            float4 vb = *(const float4*)(Wx + (size_t)(bn + row) * IDIM + k0 + lc);
            Bs[lc + 0][row] = vb.x;
            Bs[lc + 1][row] = vb.y;
            Bs[lc + 2][row] = vb.z;
            Bs[lc + 3][row] = vb.w;
        }
        __syncthreads();

#pragma unroll
        for (int kk = 0; kk < 16; kk++) {
            float a[8], b[8];
            float4 a0 = *(const float4*)(&As[kk][tm]);
            float4 a1 = *(const float4*)(&As[kk][tm + 4]);
            float4 b0 = *(const float4*)(&Bs[kk][tn]);
            float4 b1 = *(const float4*)(&Bs[kk][tn + 4]);
            a[0]=a0.x; a[1]=a0.y; a[2]=a0.z; a[3]=a0.w;
            a[4]=a1.x; a[5]=a1.y; a[6]=a1.z; a[7]=a1.w;
            b[0]=b0.x; b[1]=b0.y; b[2]=b0.z; b[3]=b0.w;
            b[4]=b1.x; b[5]=b1.y; b[6]=b1.z; b[7]=b1.w;
#pragma unroll
            for (int i = 0; i < 8; i++)
#pragma unroll
                for (int j = 0; j < 8; j++)
                    acc[i][j] = fmaf(a[i], b[j], acc[i][j]);
        }
        __syncthreads();
    }

    float bias[8];
#pragma unroll
    for (int j = 0; j < 8; j++)
        bias[j] = bx[bn + tn + j] + bh[bn + tn + j];

#pragma unroll
    for (int i = 0; i < 8; i++) {
        float* o = g_xg + (size_t)(bm + tm + i) * G4 + bn + tn;
#pragma unroll
        for (int j = 0; j < 8; j++)
            o[j] = acc[i][j] + bias[j];
    }
}

// ---------------------------------------------------------------------------
// Phase 2: persistent recurrence kernel.
// warp w = cell n = blk*8 + w, lane = batch b. c in registers.
// ---------------------------------------------------------------------------
__global__ void __launch_bounds__(256, 1) lstm_persistent_kernel(
    const float* __restrict__ Wh,
    int barrier_target_stride)    // = NBLK
{
    extern __shared__ ull smem[];                 // [2][8][1024]
    ull* ws_if = smem;                            // [cell][k] -> {wi,wf}
    ull* ws_go = smem + CELLS_PER_BLK * HDIM;     // [cell][k] -> {wg,wo}

    const int tid   = threadIdx.x;
    const int lane  = tid & 31;          // batch
    const int w     = tid >> 5;          // warp -> local cell
    const int nbase = blockIdx.x * CELLS_PER_BLK;
    const int n     = nbase + w;         // global cell

    // ---- one-time: stage & interleave this block's Wh rows into smem ----
    for (int idx = tid; idx < CELLS_PER_BLK * HDIM; idx += 256) {
        const int c = idx >> 10;
        const int k = idx & (HDIM - 1);
        const int row = nbase + c;
        const float wi = Wh[(size_t)(row         ) * HDIM + k];
        const float wf = Wh[(size_t)(row + 1*HDIM) * HDIM + k];
        const float wg = Wh[(size_t)(row + 2*HDIM) * HDIM + k];
        const float wo = Wh[(size_t)(row + 3*HDIM) * HDIM + k];
        ws_if[c * HDIM + k] = pack2(wi, wf);
        ws_go[c * HDIM + k] = pack2(wg, wo);
    }
    __syncthreads();

    const ull* __restrict__ wif = ws_if + w * HDIM;
    const ull* __restrict__ wgo = ws_go + w * HDIM;

    float c_state = 0.0f;
    const size_t out_n_base = (size_t)n * BDIM + lane;   // into g_hist per step

    for (int t = 0; t < TDIM; t++) {
        const ull* __restrict__ hin = g_hdup[t & 1] + lane;
        ull*       __restrict__ hout = g_hdup[(t + 1) & 1];

        // prefetch input-projection gates for this (b, t, n)
        const float* xgp = g_xg + ((size_t)lane * TDIM + t) * G4 + n;
        const float xi = __ldg(xgp);
        const float xf = __ldg(xgp + 1024);
        const float xgg = __ldg(xgp + 2048);
        const float xo = __ldg(xgp + 3072);

        ull aif0 = 0, aif1 = 0, ago0 = 0, ago1 = 0;   // packed fp32 zeros

#pragma unroll 4
        for (int p = 0; p < HDIM / 2; p++) {           // pairs of k
            const int k = p << 1;
            const ull h0 = __ldcg(hin + (size_t)k * BDIM);
            const ull h1 = __ldcg(hin + (size_t)(k + 1) * BDIM);
            const ull2 w_if = *(const ull2*)(wif + k);
            const ull2 w_go = *(const ull2*)(wgo + k);
            aif0 = ffma2(h0, w_if.x, aif0);
            ago0 = ffma2(h0, w_go.x, ago0);
            aif1 = ffma2(h1, w_if.y, aif1);
            ago1 = ffma2(h1, w_go.y, ago1);
        }

        const float2 vif0 = unpack2(aif0), vif1 = unpack2(aif1);
        const float2 vgo0 = unpack2(ago0), vgo1 = unpack2(ago1);
        const float gi = vif0.x + vif1.x + xi;
        const float gf = vif0.y + vif1.y + xf;
        const float gg = vgo0.x + vgo1.x + xgg;
        const float go = vgo0.y + vgo1.y + xo;

        const float si = __fdividef(1.0f, 1.0f + __expf(-gi));
        const float sf = __fdividef(1.0f, 1.0f + __expf(-gf));
        const float so = __fdividef(1.0f, 1.0f + __expf(-go));
        const float tg = tanhf(gg);

        c_state = sf * c_state + si * tg;
        const float h = so * tanhf(c_state);

        __stcg(hout + (size_t)n * BDIM + lane, pack2(h, h));
        g_hist[(size_t)t * (HDIM * BDIM) + out_n_base] = h;

        // ---- grid barrier (skip after last step) ----
        if (t < TDIM - 1) {
            __threadfence();
            __syncthreads();
            if (tid == 0) {
                atomicAdd(&g_count, 1);
                const int target = barrier_target_stride * (t + 1);
                while (ld_acquire(&g_count) < target) { }
            }
            __syncthreads();
        }
    }
}

// ---------------------------------------------------------------------------
// Phase 3: transpose g_hist [M=T*H][B=32] -> out [B][M]
// ---------------------------------------------------------------------------
__global__ void __launch_bounds__(256) transpose_out_kernel(float* __restrict__ out)
{
    __shared__ float tile[32][33];
    const size_t M  = (size_t)TDIM * HDIM;
    const size_t m0 = (size_t)blockIdx.x * 32;
    const int tx = threadIdx.x & 31;
    const int ty = threadIdx.x >> 5;      // 0..7

#pragma unroll
    for (int i = 0; i < 4; i++) {
        const int mi = ty + i * 8;
        tile[mi][tx] = g_hist[(m0 + mi) * BDIM + tx];
    }
    __syncthreads();
#pragma unroll
    for (int i = 0; i < 4; i++) {
        const int b = ty + i * 8;
        out[(size_t)b * M + m0 + tx] = tile[tx][b];
    }
}

// ---------------------------------------------------------------------------
extern "C" void kernel_launch(void* const* d_in, const int* in_sizes, int n_in,
                              void* d_out, int out_size)
{
    const float* x  = (const float*)d_in[0];   // [B,T,I]
    const float* Wx = (const float*)d_in[1];   // [4H,I]
    const float* bx = (const float*)d_in[2];   // [4H]
    const float* Wh = (const float*)d_in[3];   // [4H,H]
    const float* bh = (const float*)d_in[4];   // [4H]
    float* out = (float*)d_out;                // [B,T,H]

    (void)in_sizes; (void)n_in; (void)out_size;

    const int SMEM_BYTES = 2 * CELLS_PER_BLK * HDIM * (int)sizeof(ull);  // 128 KB
    cudaFuncSetAttribute(lstm_persistent_kernel,
                         cudaFuncAttributeMaxDynamicSharedMemorySize, SMEM_BYTES);

    init_state_kernel<<<(HDIM * BDIM + 255) / 256, 256>>>();

    dim3 ggrid(G4 / 128, (BDIM * TDIM) / 128);   // (32, 128)
    gemm_xg_kernel<<<ggrid, 256>>>(x, Wx, bx, bh);

    lstm_persistent_kernel<<<NBLK, 256, SMEM_BYTES>>>(Wh, NBLK);

    transpose_out_kernel<<<(TDIM * HDIM) / 32, 256>>>(out);
}

// round 4
// speedup vs baseline: 2.2634x; 1.0333x over previous
#include <cuda_runtime.h>

// ---------------------------------------------------------------------------
// LSTM forward: B=32, T=512, I=512, H=1024, fp32.
// Phase 1: xg = x @ Wx^T + bx + bh   (tiled fp32 GEMM, unchanged)
// Phase 2: ONE persistent kernel, 128 blocks (1/SM, all resident):
//   - block owns 8 cells; their 32 Wh rows live in smem for all 512 steps,
//     pre-interleaved as (i,f) and (g,o) f32x2 pairs
//   - h double-buffered in global as {h,h} float2 (feeds fma.rn.f32x2 directly)
//   - c state in registers for the whole sequence
//   - software grid barrier (atomic counter + acquire spin) between steps
// Phase 3: 32x32 tiled transpose [t*H+n][b] -> [b][t*H+n]
// ---------------------------------------------------------------------------

#define BDIM 32
#define TDIM 512
#define IDIM 512
#define HDIM 1024
#define G4   4096                 // 4*H
#define NBLK 128                  // persistent blocks (<= 148 SMs, 1/SM)
#define CELLS_PER_BLK 8

typedef unsigned long long ull;
struct __align__(16) ull2 { ull x, y; };

// Scratch (device globals: allocation-free per harness rules)
__device__ float g_xg[(size_t)BDIM * TDIM * G4];          // [B,T,4H]  256 MB
__device__ ull   g_hdup[2][HDIM * BDIM];                  // {h,h} packed, [n][b]
__device__ float g_hist[(size_t)TDIM * HDIM * BDIM];      // [t][n][b]  64 MB
__device__ int   g_count;                                 // barrier counter

__device__ __forceinline__ ull ffma2(ull a, ull b, ull c) {
    ull d;
    asm("fma.rn.f32x2 %0, %1, %2, %3;" : "=l"(d) : "l"(a), "l"(b), "l"(c));
    return d;
}
__device__ __forceinline__ ull pack2(float x, float y) {
    ull d;
    asm("mov.b64 %0, {%1, %2};" : "=l"(d) : "f"(x), "f"(y));
    return d;
}
__device__ __forceinline__ float2 unpack2(ull v) {
    float2 r;
    asm("mov.b64 {%0, %1}, %2;" : "=f"(r.x), "=f"(r.y) : "l"(v));
    return r;
}
__device__ __forceinline__ int ld_acquire(const int* p) {
    int v;
    asm volatile("ld.global.acquire.gpu.b32 %0, [%1];" : "=r"(v) : "l"(p));
    return v;
}

// ---------------------------------------------------------------------------
__global__ void init_state_kernel() {
    int i = blockIdx.x * blockDim.x + threadIdx.x;
    if (i < HDIM * BDIM) g_hdup[0][i] = 0ULL;
    if (i == 0) g_count = 0;
}

// ---------------------------------------------------------------------------
// Phase 1 GEMM: C[16384,4096] = X[16384,512] * Wx[4096,512]^T + (bx+bh)
// ---------------------------------------------------------------------------
__global__ void __launch_bounds__(256, 2) gemm_xg_kernel(
    const float* __restrict__ X,
    const float* __restrict__ Wx,
    const float* __restrict__ bx,
    const float* __restrict__ bh)
{
    __shared__ float As[16][128];
    __shared__ float Bs[16][128];

    const int tid = threadIdx.x;
    const int bm  = blockIdx.y * 128;
    const int bn  = blockIdx.x * 128;

    const int lr = tid >> 2;
    const int lc = (tid & 3) << 2;
    const int tm = (tid >> 4) << 3;
    const int tn = (tid & 15) << 3;

    float acc[8][8];
#pragma unroll
    for (int i = 0; i < 8; i++)
#pragma unroll
        for (int j = 0; j < 8; j++) acc[i][j] = 0.0f;

    for (int k0 = 0; k0 < IDIM; k0 += 16) {
#pragma unroll
        for (int r = 0; r < 2; r++) {
            const int row = lr + r * 64;
            float4 va = *(const float4*)(X  + (size_t)(bm + row) * IDIM + k0 + lc);
            As[lc + 0][row] = va.x;
            As[lc + 1][row] = va.y;
            As[lc + 2][row] = va.z;
            As[lc + 3][row] = va.w;
            float4 vb = *(const float4*)(Wx + (size_t)(bn + row) * IDIM + k0 + lc);
            Bs[lc + 0][row] = vb.x;
            Bs[lc + 1][row] = vb.y;
            Bs[lc + 2][row] = vb.z;
            Bs[lc + 3][row] = vb.w;
        }
        __syncthreads();

#pragma unroll
        for (int kk = 0; kk < 16; kk++) {
            float a[8], b[8];
            float4 a0 = *(const float4*)(&As[kk][tm]);
            float4 a1 = *(const float4*)(&As[kk][tm + 4]);
            float4 b0 = *(const float4*)(&Bs[kk][tn]);
            float4 b1 = *(const float4*)(&Bs[kk][tn + 4]);
            a[0]=a0.x; a[1]=a0.y; a[2]=a0.z; a[3]=a0.w;
            a[4]=a1.x; a[5]=a1.y; a[6]=a1.z; a[7]=a1.w;
            b[0]=b0.x; b[1]=b0.y; b[2]=b0.z; b[3]=b0.w;
            b[4]=b1.x; b[5]=b1.y; b[6]=b1.z; b[7]=b1.w;
#pragma unroll
            for (int i = 0; i < 8; i++)
#pragma unroll
                for (int j = 0; j < 8; j++)
                    acc[i][j] = fmaf(a[i], b[j], acc[i][j]);
        }
        __syncthreads();
    }

    float bias[8];
#pragma unroll
    for (int j = 0; j < 8; j++)
        bias[j] = bx[bn + tn + j] + bh[bn + tn + j];

#pragma unroll
    for (int i = 0; i < 8; i++) {
        float* o = g_xg + (size_t)(bm + tm + i) * G4 + bn + tn;
#pragma unroll
        for (int j = 0; j < 8; j++)
            o[j] = acc[i][j] + bias[j];
    }
}

// ---------------------------------------------------------------------------
// Phase 2: persistent recurrence kernel.
// warp w = cell n = blk*8 + w, lane = batch b. c in registers.
// ---------------------------------------------------------------------------
__global__ void __launch_bounds__(256, 1) lstm_persistent_kernel(
    const float* __restrict__ Wh,
    int barrier_target_stride)    // = NBLK
{
    extern __shared__ ull smem[];                 // [2][8][1024]
    ull* ws_if = smem;                            // [cell][k] -> {wi,wf}
    ull* ws_go = smem + CELLS_PER_BLK * HDIM;     // [cell][k] -> {wg,wo}

    const int tid   = threadIdx.x;
    const int lane  = tid & 31;          // batch
    const int w     = tid >> 5;          // warp -> local cell
    const int nbase = blockIdx.x * CELLS_PER_BLK;
    const int n     = nbase + w;         // global cell

    // ---- one-time: stage & interleave this block's Wh rows into smem ----
    for (int idx = tid; idx < CELLS_PER_BLK * HDIM; idx += 256) {
        const int c = idx >> 10;
        const int k = idx & (HDIM - 1);
        const int row = nbase + c;
        const float wi = Wh[(size_t)(row         ) * HDIM + k];
        const float wf = Wh[(size_t)(row + 1*HDIM) * HDIM + k];
        const float wg = Wh[(size_t)(row + 2*HDIM) * HDIM + k];
        const float wo = Wh[(size_t)(row + 3*HDIM) * HDIM + k];
        ws_if[c * HDIM + k] = pack2(wi, wf);
        ws_go[c * HDIM + k] = pack2(wg, wo);
    }
    __syncthreads();

    const ull* __restrict__ wif = ws_if + w * HDIM;
    const ull* __restrict__ wgo = ws_go + w * HDIM;

    float c_state = 0.0f;
    const size_t out_n_base = (size_t)n * BDIM + lane;   // into g_hist per step

    for (int t = 0; t < TDIM; t++) {
        const ull* __restrict__ hin = g_hdup[t & 1] + lane;
        ull*       __restrict__ hout = g_hdup[(t + 1) & 1];

        // prefetch input-projection gates for this (b, t, n)
        const float* xgp = g_xg + ((size_t)lane * TDIM + t) * G4 + n;
        const float xi = __ldg(xgp);
        const float xf = __ldg(xgp + 1024);
        const float xgg = __ldg(xgp + 2048);
        const float xo = __ldg(xgp + 3072);

        ull aif0 = 0, aif1 = 0, ago0 = 0, ago1 = 0;   // packed fp32 zeros

#pragma unroll 4
        for (int p = 0; p < HDIM / 2; p++) {           // pairs of k
            const int k = p << 1;
            const ull h0 = __ldcg(hin + (size_t)k * BDIM);
            const ull h1 = __ldcg(hin + (size_t)(k + 1) * BDIM);
            const ull2 w_if = *(const ull2*)(wif + k);
            const ull2 w_go = *(const ull2*)(wgo + k);
            aif0 = ffma2(h0, w_if.x, aif0);
            ago0 = ffma2(h0, w_go.x, ago0);
            aif1 = ffma2(h1, w_if.y, aif1);
            ago1 = ffma2(h1, w_go.y, ago1);
        }

        const float2 vif0 = unpack2(aif0), vif1 = unpack2(aif1);
        const float2 vgo0 = unpack2(ago0), vgo1 = unpack2(ago1);
        const float gi = vif0.x + vif1.x + xi;
        const float gf = vif0.y + vif1.y + xf;
        const float gg = vgo0.x + vgo1.x + xgg;
        const float go = vgo0.y + vgo1.y + xo;

        const float si = __fdividef(1.0f, 1.0f + __expf(-gi));
        const float sf = __fdividef(1.0f, 1.0f + __expf(-gf));
        const float so = __fdividef(1.0f, 1.0f + __expf(-go));
        const float tg = tanhf(gg);

        c_state = sf * c_state + si * tg;
        const float h = so * tanhf(c_state);

        __stcg(hout + (size_t)n * BDIM + lane, pack2(h, h));
        g_hist[(size_t)t * (HDIM * BDIM) + out_n_base] = h;

        // ---- grid barrier (skip after last step) ----
        if (t < TDIM - 1) {
            __threadfence();
            __syncthreads();
            if (tid == 0) {
                atomicAdd(&g_count, 1);
                const int target = barrier_target_stride * (t + 1);
                while (ld_acquire(&g_count) < target) { }
            }
            __syncthreads();
        }
    }
}

// ---------------------------------------------------------------------------
// Phase 3: transpose g_hist [M=T*H][B=32] -> out [B][M]
// ---------------------------------------------------------------------------
__global__ void __launch_bounds__(256) transpose_out_kernel(float* __restrict__ out)
{
    __shared__ float tile[32][33];
    const size_t M  = (size_t)TDIM * HDIM;
    const size_t m0 = (size_t)blockIdx.x * 32;
    const int tx = threadIdx.x & 31;
    const int ty = threadIdx.x >> 5;      // 0..7

#pragma unroll
    for (int i = 0; i < 4; i++) {
        const int mi = ty + i * 8;
        tile[mi][tx] = g_hist[(m0 + mi) * BDIM + tx];
    }
    __syncthreads();
#pragma unroll
    for (int i = 0; i < 4; i++) {
        const int b = ty + i * 8;
        out[(size_t)b * M + m0 + tx] = tile[tx][b];
    }
}

// ---------------------------------------------------------------------------
extern "C" void kernel_launch(void* const* d_in, const int* in_sizes, int n_in,
                              void* d_out, int out_size)
{
    const float* x  = (const float*)d_in[0];   // [B,T,I]
    const float* Wx = (const float*)d_in[1];   // [4H,I]
    const float* bx = (const float*)d_in[2];   // [4H]
    const float* Wh = (const float*)d_in[3];   // [4H,H]
    const float* bh = (const float*)d_in[4];   // [4H]
    float* out = (float*)d_out;                // [B,T,H]

    (void)in_sizes; (void)n_in; (void)out_size;

    const int SMEM_BYTES = 2 * CELLS_PER_BLK * HDIM * (int)sizeof(ull);  // 128 KB
    cudaFuncSetAttribute(lstm_persistent_kernel,
                         cudaFuncAttributeMaxDynamicSharedMemorySize, SMEM_BYTES);

    init_state_kernel<<<(HDIM * BDIM + 255) / 256, 256>>>();

    dim3 ggrid(G4 / 128, (BDIM * TDIM) / 128);   // (32, 128)
    gemm_xg_kernel<<<ggrid, 256>>>(x, Wx, bx, bh);

    lstm_persistent_kernel<<<NBLK, 256, SMEM_BYTES>>>(Wh, NBLK);

    transpose_out_kernel<<<(TDIM * HDIM) / 32, 256>>>(out);
}

// round 5
// speedup vs baseline: 4.5741x; 2.0209x over previous
#include <cuda_runtime.h>

#define BDIM 32
#define TDIM 512
#define IDIM 512
#define HDIM 1024
#define G4   4096
#define NBLK 128
#define CPB  8                  // cells per block
#define HPAD 516                // smem h row stride (floats): bank=(4b+k)%32, conflict-free

typedef unsigned long long ull;
struct __align__(16) ull2 { ull x, y; };

__device__ float g_xg[(size_t)BDIM * TDIM * G4];      // [B,T,4H]
__device__ float g_hbk[2][BDIM * HDIM];               // h as [b][k], double-buffered
__device__ float g_hist[(size_t)TDIM * HDIM * BDIM];  // [t][n][b]
__device__ int   g_count;

__device__ __forceinline__ ull ffma2(ull a, ull b, ull c) {
    ull d; asm("fma.rn.f32x2 %0, %1, %2, %3;" : "=l"(d) : "l"(a), "l"(b), "l"(c));
    return d;
}
__device__ __forceinline__ ull pack2(float x, float y) {
    ull d; asm("mov.b64 %0, {%1, %2};" : "=l"(d) : "f"(x), "f"(y));
    return d;
}
__device__ __forceinline__ float2 unpack2(ull v) {
    float2 r; asm("mov.b64 {%0, %1}, %2;" : "=f"(r.x), "=f"(r.y) : "l"(v));
    return r;
}
__device__ __forceinline__ int ld_acquire(const int* p) {
    int v; asm volatile("ld.global.acquire.gpu.b32 %0, [%1];" : "=r"(v) : "l"(p));
    return v;
}

__global__ void init_state_kernel() {
    int i = blockIdx.x * blockDim.x + threadIdx.x;
    if (i < BDIM * HDIM) g_hbk[0][i] = 0.0f;
    if (i == 0) g_count = 0;
}

// ---------------------------------------------------------------------------
// Phase 1 GEMM (f32x2): C[16384,4096] = X[16384,512]*Wx^T + (bx+bh)
// ---------------------------------------------------------------------------
__global__ void __launch_bounds__(256, 2) gemm_xg_kernel(
    const float* __restrict__ X, const float* __restrict__ Wx,
    const float* __restrict__ bx, const float* __restrict__ bh)
{
    __shared__ float As[16][128];
    __shared__ float Bs[16][128];

    const int tid = threadIdx.x;
    const int bm  = blockIdx.y * 128;
    const int bn  = blockIdx.x * 128;
    const int lr = tid >> 2;
    const int lc = (tid & 3) << 2;
    const int tm = (tid >> 4) << 3;
    const int tn = (tid & 15) << 3;

    ull acc2[4][8];
#pragma unroll
    for (int ip = 0; ip < 4; ip++)
#pragma unroll
        for (int j = 0; j < 8; j++) acc2[ip][j] = 0ULL;

    for (int k0 = 0; k0 < IDIM; k0 += 16) {
#pragma unroll
        for (int r = 0; r < 2; r++) {
            const int row = lr + r * 64;
            float4 va = *(const float4*)(X  + (size_t)(bm + row) * IDIM + k0 + lc);
            As[lc + 0][row] = va.x; As[lc + 1][row] = va.y;
            As[lc + 2][row] = va.z; As[lc + 3][row] = va.w;
            float4 vb = *(const float4*)(Wx + (size_t)(bn + row) * IDIM + k0 + lc);
            Bs[lc + 0][row] = vb.x; Bs[lc + 1][row] = vb.y;
            Bs[lc + 2][row] = vb.z; Bs[lc + 3][row] = vb.w;
        }
        __syncthreads();

#pragma unroll
        for (int kk = 0; kk < 16; kk++) {
            const ull* ap = (const ull*)(&As[kk][tm]);
            ull a2[4] = {ap[0], ap[1], ap[2], ap[3]};
            float4 b0 = *(const float4*)(&Bs[kk][tn]);
            float4 b1 = *(const float4*)(&Bs[kk][tn + 4]);
            ull bd[8];
            bd[0] = pack2(b0.x, b0.x); bd[1] = pack2(b0.y, b0.y);
            bd[2] = pack2(b0.z, b0.z); bd[3] = pack2(b0.w, b0.w);
            bd[4] = pack2(b1.x, b1.x); bd[5] = pack2(b1.y, b1.y);
            bd[6] = pack2(b1.z, b1.z); bd[7] = pack2(b1.w, b1.w);
#pragma unroll
            for (int ip = 0; ip < 4; ip++)
#pragma unroll
                for (int j = 0; j < 8; j++)
                    acc2[ip][j] = ffma2(a2[ip], bd[j], acc2[ip][j]);
        }
        __syncthreads();
    }

    float bias[8];
#pragma unroll
    for (int j = 0; j < 8; j++) bias[j] = bx[bn + tn + j] + bh[bn + tn + j];

#pragma unroll
    for (int ip = 0; ip < 4; ip++) {
        float lo[8], hi[8];
#pragma unroll
        for (int j = 0; j < 8; j++) {
            float2 v = unpack2(acc2[ip][j]);
            lo[j] = v.x + bias[j];
            hi[j] = v.y + bias[j];
        }
        float* o0 = g_xg + (size_t)(bm + tm + 2 * ip)     * G4 + bn + tn;
        float* o1 = g_xg + (size_t)(bm + tm + 2 * ip + 1) * G4 + bn + tn;
        *(float4*)(o0)     = make_float4(lo[0], lo[1], lo[2], lo[3]);
        *(float4*)(o0 + 4) = make_float4(lo[4], lo[5], lo[6], lo[7]);
        *(float4*)(o1)     = make_float4(hi[0], hi[1], hi[2], hi[3]);
        *(float4*)(o1 + 4) = make_float4(hi[4], hi[5], hi[6], hi[7]);
    }
}

// ---------------------------------------------------------------------------
// Phase 2: persistent recurrence. warp = cell, lane = batch.
// Wh pairs in smem (128 KB); h staged per block per step in two 64 KB halves.
// ---------------------------------------------------------------------------
__global__ void __launch_bounds__(256, 1) lstm_persistent_kernel(
    const float* __restrict__ Wh)
{
    extern __shared__ char smem_raw[];
    ull*   wsm = (ull*)smem_raw;                          // [2][CPB][HDIM] pairs
    float* hsm = (float*)(smem_raw + 2 * CPB * HDIM * 8); // [32][HPAD]

    const int tid = threadIdx.x;
    const int l   = tid & 31;                 // lane = batch
    const int w   = tid >> 5;                 // warp = local cell
    const int n   = blockIdx.x * CPB + w;

    // one-time: interleave this block's Wh rows into smem as f32x2 gate pairs
    for (int idx = tid; idx < CPB * HDIM; idx += 256) {
        const int c = idx >> 10, k = idx & (HDIM - 1);
        const int row = blockIdx.x * CPB + c;
        wsm[c * HDIM + k] =
            pack2(Wh[(size_t)row * HDIM + k], Wh[(size_t)(row + HDIM) * HDIM + k]);
        wsm[CPB * HDIM + c * HDIM + k] =
            pack2(Wh[(size_t)(row + 2 * HDIM) * HDIM + k],
                  Wh[(size_t)(row + 3 * HDIM) * HDIM + k]);
    }
    __syncthreads();

    const ull* wif = wsm + w * HDIM;
    const ull* wgo = wsm + CPB * HDIM + w * HDIM;

    // staging map: thread -> (b = 4w + l/8, k base = 4*(l&7))
    const int sb = (w << 2) + (l >> 3);
    const int sk = (l & 7) << 2;

    float cst = 0.0f;

    for (int t = 0; t < TDIM; t++) {
        const float* hin = g_hbk[t & 1];

        // prefetch input-projection gates (used ~8K cycles later)
        const float* xgp = g_xg + ((size_t)l * TDIM + t) * G4 + n;
        const float xi  = __ldg(xgp);
        const float xf  = __ldg(xgp + 1024);
        const float xgg = __ldg(xgp + 2048);
        const float xo  = __ldg(xgp + 3072);

        ull aif[4] = {0, 0, 0, 0}, ago[4] = {0, 0, 0, 0};

#pragma unroll
        for (int half = 0; half < 2; half++) {
            // stage 512 k's: coalesced LDG.128, conflict-free STS.128
            const float* src = hin + (size_t)sb * HDIM + (half << 9) + sk;
            float* dst = hsm + sb * HPAD + sk;
#pragma unroll
            for (int r = 0; r < 16; r++)
                *(float4*)(dst + (r << 5)) = __ldcg((const float4*)(src + (r << 5)));
            __syncthreads();

            const float* hp  = hsm + l * HPAD;
            const ull* wifh = wif + (half << 9);
            const ull* wgoh = wgo + (half << 9);
#pragma unroll 8
            for (int j = 0; j < 128; j++) {
                const float4 h4 = *(const float4*)(hp + (j << 2));
                const ull2 wiA = *(const ull2*)(wifh + (j << 2));
                const ull2 wiB = *(const ull2*)(wifh + (j << 2) + 2);
                const ull2 wgA = *(const ull2*)(wgoh + (j << 2));
                const ull2 wgB = *(const ull2*)(wgoh + (j << 2) + 2);
                const ull hd0 = pack2(h4.x, h4.x), hd1 = pack2(h4.y, h4.y);
                const ull hd2 = pack2(h4.z, h4.z), hd3 = pack2(h4.w, h4.w);
                aif[0] = ffma2(hd0, wiA.x, aif[0]); ago[0] = ffma2(hd0, wgA.x, ago[0]);
                aif[1] = ffma2(hd1, wiA.y, aif[1]); ago[1] = ffma2(hd1, wgA.y, ago[1]);
                aif[2] = ffma2(hd2, wiB.x, aif[2]); ago[2] = ffma2(hd2, wgB.x, ago[2]);
                aif[3] = ffma2(hd3, wiB.y, aif[3]); ago[3] = ffma2(hd3, wgB.y, ago[3]);
            }
            __syncthreads();
        }

        const float2 i0 = unpack2(aif[0]), i1 = unpack2(aif[1]);
        const float2 i2 = unpack2(aif[2]), i3 = unpack2(aif[3]);
        const float2 g0 = unpack2(ago[0]), g1 = unpack2(ago[1]);
        const float2 g2 = unpack2(ago[2]), g3 = unpack2(ago[3]);
        const float gi = (i0.x + i1.x) + (i2.x + i3.x) + xi;
        const float gf = (i0.y + i1.y) + (i2.y + i3.y) + xf;
        const float gg = (g0.x + g1.x) + (g2.x + g3.x) + xgg;
        const float go = (g0.y + g1.y) + (g2.y + g3.y) + xo;

        const float si = __fdividef(1.0f, 1.0f + __expf(-gi));
        const float sf = __fdividef(1.0f, 1.0f + __expf(-gf));
        const float so = __fdividef(1.0f, 1.0f + __expf(-go));
        cst = sf * cst + si * tanhf(gg);
        const float h = so * tanhf(cst);

        g_hbk[(t + 1) & 1][(size_t)l * HDIM + n] = h;                  // scatter [b][k]
        g_hist[(size_t)t * (HDIM * BDIM) + (size_t)n * BDIM + l] = h;  // coalesced

        if (t < TDIM - 1) {
            __threadfence();
            __syncthreads();
            if (tid == 0) {
                atomicAdd(&g_count, 1);
                while (ld_acquire(&g_count) < NBLK * (t + 1)) { }
            }
            __syncthreads();
        }
    }
}

// ---------------------------------------------------------------------------
__global__ void __launch_bounds__(256) transpose_out_kernel(float* __restrict__ out)
{
    __shared__ float tile[32][33];
    const size_t M  = (size_t)TDIM * HDIM;
    const size_t m0 = (size_t)blockIdx.x * 32;
    const int tx = threadIdx.x & 31;
    const int ty = threadIdx.x >> 5;

#pragma unroll
    for (int i = 0; i < 4; i++)
        tile[ty + i * 8][tx] = g_hist[(m0 + ty + i * 8) * BDIM + tx];
    __syncthreads();
#pragma unroll
    for (int i = 0; i < 4; i++) {
        const int b = ty + i * 8;
        out[(size_t)b * M + m0 + tx] = tile[tx][b];
    }
}

// ---------------------------------------------------------------------------
extern "C" void kernel_launch(void* const* d_in, const int* in_sizes, int n_in,
                              void* d_out, int out_size)
{
    const float* x  = (const float*)d_in[0];
    const float* Wx = (const float*)d_in[1];
    const float* bx = (const float*)d_in[2];
    const float* Wh = (const float*)d_in[3];
    const float* bh = (const float*)d_in[4];
    float* out = (float*)d_out;
    (void)in_sizes; (void)n_in; (void)out_size;

    const int SMEM_BYTES = 2 * CPB * HDIM * 8 + 32 * HPAD * 4;   // 197120 B
    cudaFuncSetAttribute(lstm_persistent_kernel,
                         cudaFuncAttributeMaxDynamicSharedMemorySize, SMEM_BYTES);

    init_state_kernel<<<(BDIM * HDIM + 255) / 256, 256>>>();

    dim3 ggrid(G4 / 128, (BDIM * TDIM) / 128);
    gemm_xg_kernel<<<ggrid, 256>>>(x, Wx, bx, bh);

    lstm_persistent_kernel<<<NBLK, 256, SMEM_BYTES>>>(Wh);

    transpose_out_kernel<<<(TDIM * HDIM) / 32, 256>>>(out);
}

// round 6
// speedup vs baseline: 6.5101x; 1.4233x over previous
#include <cuda_runtime.h>

#define BDIM 32
#define TDIM 512
#define IDIM 512
#define HDIM 1024
#define G4   4096
#define NBLK 128
#define CPB  8
#define HPAD 36                 // hsm row stride (floats): banks (4l+e), conflict-free

typedef unsigned long long ull;

__device__ float g_xg[(size_t)BDIM * TDIM * G4];   // [B,T,4H]
__device__ float g_hkb[2][HDIM * BDIM];            // h as [k][b], double-buffered
__device__ int   g_count;

__device__ __forceinline__ ull ffma2(ull a, ull b, ull c) {
    ull d; asm("fma.rn.f32x2 %0, %1, %2, %3;" : "=l"(d) : "l"(a), "l"(b), "l"(c));
    return d;
}
__device__ __forceinline__ ull add2(ull a, ull b) {
    ull d; asm("add.rn.f32x2 %0, %1, %2;" : "=l"(d) : "l"(a), "l"(b));
    return d;
}
__device__ __forceinline__ ull pack2(float x, float y) {
    ull d; asm("mov.b64 %0, {%1, %2};" : "=l"(d) : "f"(x), "f"(y));
    return d;
}
__device__ __forceinline__ float2 unpack2(ull v) {
    float2 r; asm("mov.b64 {%0, %1}, %2;" : "=f"(r.x), "=f"(r.y) : "l"(v));
    return r;
}
__device__ __forceinline__ int ld_acquire(const int* p) {
    int v; asm volatile("ld.global.acquire.gpu.b32 %0, [%1];" : "=r"(v) : "l"(p));
    return v;
}

__global__ void init_state_kernel() {
    int i = blockIdx.x * blockDim.x + threadIdx.x;
    if (i < HDIM * BDIM) g_hkb[0][i] = 0.0f;
    if (i == 0) g_count = 0;
}

// ---------------------------------------------------------------------------
// Phase 1 GEMM (f32x2): xg[16384,4096] = X*Wx^T + (bx+bh)
// ---------------------------------------------------------------------------
__global__ void __launch_bounds__(256, 2) gemm_xg_kernel(
    const float* __restrict__ X, const float* __restrict__ Wx,
    const float* __restrict__ bx, const float* __restrict__ bh)
{
    __shared__ float As[16][128];
    __shared__ float Bs[16][128];

    const int tid = threadIdx.x;
    const int bm  = blockIdx.y * 128;
    const int bn  = blockIdx.x * 128;
    const int lr = tid >> 2;
    const int lc = (tid & 3) << 2;
    const int tm = (tid >> 4) << 3;
    const int tn = (tid & 15) << 3;

    ull acc2[4][8];
#pragma unroll
    for (int ip = 0; ip < 4; ip++)
#pragma unroll
        for (int j = 0; j < 8; j++) acc2[ip][j] = 0ULL;

    for (int k0 = 0; k0 < IDIM; k0 += 16) {
#pragma unroll
        for (int r = 0; r < 2; r++) {
            const int row = lr + r * 64;
            float4 va = *(const float4*)(X  + (size_t)(bm + row) * IDIM + k0 + lc);
            As[lc + 0][row] = va.x; As[lc + 1][row] = va.y;
            As[lc + 2][row] = va.z; As[lc + 3][row] = va.w;
            float4 vb = *(const float4*)(Wx + (size_t)(bn + row) * IDIM + k0 + lc);
            Bs[lc + 0][row] = vb.x; Bs[lc + 1][row] = vb.y;
            Bs[lc + 2][row] = vb.z; Bs[lc + 3][row] = vb.w;
        }
        __syncthreads();

#pragma unroll
        for (int kk = 0; kk < 16; kk++) {
            const ull* ap = (const ull*)(&As[kk][tm]);
            ull a2[4] = {ap[0], ap[1], ap[2], ap[3]};
            float4 b0 = *(const float4*)(&Bs[kk][tn]);
            float4 b1 = *(const float4*)(&Bs[kk][tn + 4]);
            ull bd[8];
            bd[0] = pack2(b0.x, b0.x); bd[1] = pack2(b0.y, b0.y);
            bd[2] = pack2(b0.z, b0.z); bd[3] = pack2(b0.w, b0.w);
            bd[4] = pack2(b1.x, b1.x); bd[5] = pack2(b1.y, b1.y);
            bd[6] = pack2(b1.z, b1.z); bd[7] = pack2(b1.w, b1.w);
#pragma unroll
            for (int ip = 0; ip < 4; ip++)
#pragma unroll
                for (int j = 0; j < 8; j++)
                    acc2[ip][j] = ffma2(a2[ip], bd[j], acc2[ip][j]);
        }
        __syncthreads();
    }

    float bias[8];
#pragma unroll
    for (int j = 0; j < 8; j++) bias[j] = bx[bn + tn + j] + bh[bn + tn + j];

#pragma unroll
    for (int ip = 0; ip < 4; ip++) {
        float lo[8], hi[8];
#pragma unroll
        for (int j = 0; j < 8; j++) {
            float2 v = unpack2(acc2[ip][j]);
            lo[j] = v.x + bias[j];
            hi[j] = v.y + bias[j];
        }
        float* o0 = g_xg + (size_t)(bm + tm + 2 * ip)     * G4 + bn + tn;
        float* o1 = g_xg + (size_t)(bm + tm + 2 * ip + 1) * G4 + bn + tn;
        *(float4*)(o0)     = make_float4(lo[0], lo[1], lo[2], lo[3]);
        *(float4*)(o0 + 4) = make_float4(lo[4], lo[5], lo[6], lo[7]);
        *(float4*)(o1)     = make_float4(hi[0], hi[1], hi[2], hi[3]);
        *(float4*)(o1 + 4) = make_float4(hi[4], hi[5], hi[6], hi[7]);
    }
}

// ---------------------------------------------------------------------------
// Phase 2: persistent recurrence. warp = cell, lane = k-slice; Wh in registers
// as f32x2 cross-gate pairs; h staged via cp.async into smem [k][b] each step.
// Batch processed in 4 passes of 8; xor reduce-scatter -> lane = (b, gate).
// ---------------------------------------------------------------------------
__global__ void __launch_bounds__(256, 1) lstm_persistent_kernel(
    const float* __restrict__ Wh,
    float* __restrict__ out)
{
    extern __shared__ float hsm[];              // [HDIM][HPAD]

    const int tid = threadIdx.x;
    const int l   = tid & 31;                   // lane = k-slice
    const int w   = tid >> 5;                   // warp = local cell
    const int n   = blockIdx.x * CPB + w;       // global cell

    // ---- one-time: Wh rows for cell n into registers (f32x2 gate pairs) ----
    ull wif[32], wgo[32];
#pragma unroll
    for (int j = 0; j < 32; j++) {
        const int k = (j << 5) + l;
        wif[j] = pack2(Wh[(size_t)n * HDIM + k],
                       Wh[(size_t)(n + HDIM) * HDIM + k]);
        wgo[j] = pack2(Wh[(size_t)(n + 2 * HDIM) * HDIM + k],
                       Wh[(size_t)(n + 3 * HDIM) * HDIM + k]);
    }

    // lane decomposition for reduce-scatter result
    const int  bit4 = (l >> 4) & 1, bit3 = (l >> 3) & 1, bit2 = (l >> 2) & 1;
    const int  bit1 = (l >> 1) & 1, bit0 = l & 1;
    const int  gate = l & 3;                    // 0=i 1=f 2=g 3=o
    const int  bsub = l >> 2;                   // batch index within pass (0..7)
    const bool isG  = (gate == 2);
    const int  gbase = l & ~3;

    // staging addresses (cp.async, 16B each)
    const unsigned hrow0 = (unsigned)(tid >> 3);       // k base
    const unsigned hcol  = (unsigned)((tid & 7) << 2); // b base
    const unsigned sbase = (unsigned)__cvta_generic_to_shared(hsm);

    float cst[4] = {0.0f, 0.0f, 0.0f, 0.0f};

    for (int t = 0; t < TDIM; t++) {
        // ---- stage h(t): g_hkb[t&1] ([k][b], coalesced) -> hsm[k][b] ----
        {
            const float* src = g_hkb[t & 1] + (tid << 2);
#pragma unroll
            for (int r = 0; r < 32; r++) {
                const unsigned d = sbase + ((hrow0 + (r << 5)) * HPAD + hcol) * 4u;
                asm volatile("cp.async.cg.shared.global [%0], [%1], 16;"
                             :: "r"(d), "l"(src + (r << 10)) : "memory");
            }
            asm volatile("cp.async.commit_group;" ::: "memory");
        }

        // prefetch xg for all 4 passes (lane = (b, gate))
        float xgv[4];
#pragma unroll
        for (int p = 0; p < 4; p++)
            xgv[p] = __ldg(g_xg + ((size_t)(p * 8 + bsub) * TDIM + t) * G4
                           + (size_t)gate * HDIM + n);

        asm volatile("cp.async.wait_group 0;" ::: "memory");
        __syncthreads();

#pragma unroll
        for (int p = 0; p < 4; p++) {
            ull aif[8], ago[8];
#pragma unroll
            for (int b = 0; b < 8; b++) { aif[b] = 0ULL; ago[b] = 0ULL; }

            const float* hp = hsm + (size_t)l * HPAD + (p << 3);
#pragma unroll
            for (int j = 0; j < 32; j++) {
                const float4 h0 = *(const float4*)(hp + (size_t)(j << 5) * HPAD);
                const float4 h1 = *(const float4*)(hp + (size_t)(j << 5) * HPAD + 4);
                const ull hd0 = pack2(h0.x, h0.x), hd1 = pack2(h0.y, h0.y);
                const ull hd2 = pack2(h0.z, h0.z), hd3 = pack2(h0.w, h0.w);
                const ull hd4 = pack2(h1.x, h1.x), hd5 = pack2(h1.y, h1.y);
                const ull hd6 = pack2(h1.z, h1.z), hd7 = pack2(h1.w, h1.w);
                aif[0] = ffma2(hd0, wif[j], aif[0]); ago[0] = ffma2(hd0, wgo[j], ago[0]);
                aif[1] = ffma2(hd1, wif[j], aif[1]); ago[1] = ffma2(hd1, wgo[j], ago[1]);
                aif[2] = ffma2(hd2, wif[j], aif[2]); ago[2] = ffma2(hd2, wgo[j], ago[2]);
                aif[3] = ffma2(hd3, wif[j], aif[3]); ago[3] = ffma2(hd3, wgo[j], ago[3]);
                aif[4] = ffma2(hd4, wif[j], aif[4]); ago[4] = ffma2(hd4, wgo[j], ago[4]);
                aif[5] = ffma2(hd5, wif[j], aif[5]); ago[5] = ffma2(hd5, wgo[j], ago[5]);
                aif[6] = ffma2(hd6, wif[j], aif[6]); ago[6] = ffma2(hd6, wgo[j], ago[6]);
                aif[7] = ffma2(hd7, wif[j], aif[7]); ago[7] = ffma2(hd7, wgo[j], ago[7]);
            }

            // ---- reduce-scatter: sum over 32 lanes, scatter (b, gate) ----
            ull VA[4], VG[4];
#pragma unroll
            for (int v = 0; v < 4; v++) {
                VA[v] = add2(bit4 ? aif[4 + v] : aif[v],
                             __shfl_xor_sync(0xffffffffu, bit4 ? aif[v] : aif[4 + v], 16));
                VG[v] = add2(bit4 ? ago[4 + v] : ago[v],
                             __shfl_xor_sync(0xffffffffu, bit4 ? ago[v] : ago[4 + v], 16));
            }
            ull WA[2], WG[2];
#pragma unroll
            for (int v = 0; v < 2; v++) {
                WA[v] = add2(bit3 ? VA[2 + v] : VA[v],
                             __shfl_xor_sync(0xffffffffu, bit3 ? VA[v] : VA[2 + v], 8));
                WG[v] = add2(bit3 ? VG[2 + v] : VG[v],
                             __shfl_xor_sync(0xffffffffu, bit3 ? VG[v] : VG[2 + v], 8));
            }
            const ull XA = add2(bit2 ? WA[1] : WA[0],
                                __shfl_xor_sync(0xffffffffu, bit2 ? WA[0] : WA[1], 4));
            const ull XG = add2(bit2 ? WG[1] : WG[0],
                                __shfl_xor_sync(0xffffffffu, bit2 ? WG[0] : WG[1], 4));
            const ull Y = add2(bit1 ? XG : XA,
                               __shfl_xor_sync(0xffffffffu, bit1 ? XA : XG, 2));
            const float2 y2 = unpack2(Y);
            float F = (bit0 ? y2.y : y2.x)
                    + __shfl_xor_sync(0xffffffffu, bit0 ? y2.x : y2.y, 1);

            // ---- gate nonlinearity: sigmoid via tanh identity ----
            F += xgv[p];
            float a = tanhf(isG ? F : 0.5f * F);
            a = isG ? a : 0.5f * (1.0f + a);

            const float vi = __shfl_sync(0xffffffffu, a, gbase);
            const float vf = __shfl_sync(0xffffffffu, a, gbase + 1);
            const float vg = __shfl_sync(0xffffffffu, a, gbase + 2);
            const float vo = __shfl_sync(0xffffffffu, a, gbase + 3);

            cst[p] = vf * cst[p] + vi * vg;
            const float h = vo * tanhf(cst[p]);

            if (gate == 0) {
                const int b = p * 8 + bsub;
                g_hkb[(t + 1) & 1][(n << 5) + b] = h;                     // [k][b]
                out[((size_t)b * TDIM + t) * HDIM + n] = h;               // [B,T,H]
            }
        }

        // ---- grid barrier ----
        if (t < TDIM - 1) {
            __threadfence();
            __syncthreads();
            if (tid == 0) {
                atomicAdd(&g_count, 1);
                while (ld_acquire(&g_count) < NBLK * (t + 1)) { }
            }
            __syncthreads();
        }
    }
}

// ---------------------------------------------------------------------------
extern "C" void kernel_launch(void* const* d_in, const int* in_sizes, int n_in,
                              void* d_out, int out_size)
{
    const float* x  = (const float*)d_in[0];
    const float* Wx = (const float*)d_in[1];
    const float* bx = (const float*)d_in[2];
    const float* Wh = (const float*)d_in[3];
    const float* bh = (const float*)d_in[4];
    float* out = (float*)d_out;
    (void)in_sizes; (void)n_in; (void)out_size;

    const int SMEM_BYTES = HDIM * HPAD * (int)sizeof(float);   // 147456
    cudaFuncSetAttribute(lstm_persistent_kernel,
                         cudaFuncAttributeMaxDynamicSharedMemorySize, SMEM_BYTES);

    init_state_kernel<<<(HDIM * BDIM + 255) / 256, 256>>>();

    dim3 ggrid(G4 / 128, (BDIM * TDIM) / 128);
    gemm_xg_kernel<<<ggrid, 256>>>(x, Wx, bx, bh);

    lstm_persistent_kernel<<<NBLK, 256, SMEM_BYTES>>>(Wh, out);
}